// round 7
// baseline (speedup 1.0000x reference)
#include <cuda_runtime.h>
#include <cooperative_groups.h>
#include <math.h>

namespace cg = cooperative_groups;
typedef unsigned long long ull;

#define BB   32
#define NN_  400
#define TT   315
#define TP   320      // padded T (row stride of s)
#define DD   512
#define HH   256

// ---------------- scratch (static device globals; no allocations) ----------------
__device__ float g_tA[TT * DD];                 // text @ A^T            [T, D]
__device__ float g_s [BB * NN_ * TP + 128];     // affinity / s1 (padded rows) + over-read pad
__device__ float g_f1[BB * TT * DD];            // mixed features        [B, T, D]
__device__ float g_th[TT * HH];                 // text @ Wh_bottom      [T, H]
__device__ float g_h [BB * TT * HH];            // hidden                [B*T, H]

// ---------------- f32x2 helpers ----------------
__device__ __forceinline__ void fma2(ull& d, ull a, ull b) {
    asm("fma.rn.f32x2 %0, %1, %2, %0;" : "+l"(d) : "l"(a), "l"(b));
}
__device__ __forceinline__ ull dup2(float x) {
    ull r; unsigned u = __float_as_uint(x);
    asm("mov.b64 %0, {%1, %1};" : "=l"(r) : "r"(u));
    return r;
}
__device__ __forceinline__ ull pack2(float x, float y) {
    ull r;
    asm("mov.b64 %0, {%1, %2};" : "=l"(r) : "r"(__float_as_uint(x)), "r"(__float_as_uint(y)));
    return r;
}
__device__ __forceinline__ float2 upk(ull v) {
    float2 f; asm("mov.b64 {%0, %1}, %2;" : "=f"(f.x), "=f"(f.y) : "l"(v));
    return f;
}

// ============================================================================
// Unified 128x128 GEMM, BK=16, 256 threads, 8x8 micro-tile, fma.rn.f32x2.
// ALOAD: 0 = A[M,K] row-major k-contig; 1 = A[K,M] m-contig (k-major)
// BLOAD: 0 = NT: B[N,K] k-contig;      1 = NN: B[K,N] n-contig
// EPI:   0 = plain store; 1 = relu(C + addrow[(m%TT)*ldc + n] + bias[n])
// A-tile is stored DUPLICATED in smem: AsD[kk][2m]=AsD[kk][2m+1]=a(m,kk),
// so the compute loop reads ready-made (a,a) f32x2 operands.
// ============================================================================
template<int ALOAD, int BLOAD, int EPI>
__global__ __launch_bounds__(256, 2)
void gemm128(const float* __restrict__ A, const float* __restrict__ B, float* __restrict__ C,
             int M, int Nvalid, int K, int lda, int ldb, int ldc, int Ns,
             long long sA, long long sB, long long sC,
             const float* __restrict__ addrow, const float* __restrict__ bias)
{
    __shared__ __align__(16) float AsD[16][264];
    __shared__ __align__(16) float Bs[16][136];

    A += (long long)blockIdx.z * sA;
    B += (long long)blockIdx.z * sB;
    C += (long long)blockIdx.z * sC;

    const int bm = blockIdx.x * 128, bn = blockIdx.y * 128;
    const int tid = threadIdx.x;
    const int w = tid >> 5, l = tid & 31;
    const int wr = w >> 1, wc = w & 1, lr = l >> 3, lc = l & 7;
    const int rowb = wr * 32 + lr * 8;     // thread's 8 output rows
    const int colb = wc * 64 + lc * 8;     // thread's 8 output cols

    ull acc[8][4];
#pragma unroll
    for (int i = 0; i < 8; i++)
#pragma unroll
        for (int j = 0; j < 4; j++) acc[i][j] = 0ull;

    // ---- loader index setup ----
    int arow = 0, akc = 0, akk2 = 0, am4 = 0;
    const float* Ap;
    bool aok = true;
    if (ALOAD == 0) {
        arow = tid & 127; akc = (tid >> 7) << 3;
        aok = (bm + arow) < M;
        Ap = A + (size_t)(bm + arow) * lda + akc;
    } else {
        akk2 = tid >> 5; am4 = l << 2;
        Ap = A + (size_t)(akk2 * 2) * lda + bm + am4;
    }
    int bcol = 0, bkc = 0, bkk = 0, bnc = 0;
    const float* Bp;
    bool bok = true;
    if (BLOAD == 0) {
        bcol = tid & 127; bkc = (tid >> 7) << 3;
        bok = (bn + bcol) < Nvalid;
        Bp = B + (size_t)(bn + bcol) * ldb + bkc;
    } else {
        bkk = tid >> 4; bnc = (tid & 15) << 3;
        bok = (bn + bnc) < Nvalid;
        Bp = B + (size_t)bkk * ldb + bn + bnc;
    }

    const float4 Z = make_float4(0.f, 0.f, 0.f, 0.f);
    float4 ra0, ra1, rb0, rb1;

    // initial tile load (k0 = 0)
    if (ALOAD == 0) {
        ra0 = aok ? *(const float4*)(Ap) : Z;
        ra1 = aok ? *(const float4*)(Ap + 4) : Z;
    } else {
        ra0 = *(const float4*)(Ap);
        ra1 = *(const float4*)(Ap + lda);
    }
    rb0 = bok ? *(const float4*)(Bp) : Z;
    rb1 = bok ? *(const float4*)(Bp + 4) : Z;

    for (int k0 = 0;;) {
        __syncthreads();
        // ---- store staged tile to smem ----
        if (ALOAD == 0) {
            *(ull*)&AsD[akc + 0][2 * arow] = dup2(ra0.x);
            *(ull*)&AsD[akc + 1][2 * arow] = dup2(ra0.y);
            *(ull*)&AsD[akc + 2][2 * arow] = dup2(ra0.z);
            *(ull*)&AsD[akc + 3][2 * arow] = dup2(ra0.w);
            *(ull*)&AsD[akc + 4][2 * arow] = dup2(ra1.x);
            *(ull*)&AsD[akc + 5][2 * arow] = dup2(ra1.y);
            *(ull*)&AsD[akc + 6][2 * arow] = dup2(ra1.z);
            *(ull*)&AsD[akc + 7][2 * arow] = dup2(ra1.w);
        } else {
            *(float4*)&AsD[akk2 * 2][2 * am4]         = make_float4(ra0.x, ra0.x, ra0.y, ra0.y);
            *(float4*)&AsD[akk2 * 2][2 * am4 + 4]     = make_float4(ra0.z, ra0.z, ra0.w, ra0.w);
            *(float4*)&AsD[akk2 * 2 + 1][2 * am4]     = make_float4(ra1.x, ra1.x, ra1.y, ra1.y);
            *(float4*)&AsD[akk2 * 2 + 1][2 * am4 + 4] = make_float4(ra1.z, ra1.z, ra1.w, ra1.w);
        }
        if (BLOAD == 0) {
            Bs[bkc + 0][bcol] = rb0.x; Bs[bkc + 1][bcol] = rb0.y;
            Bs[bkc + 2][bcol] = rb0.z; Bs[bkc + 3][bcol] = rb0.w;
            Bs[bkc + 4][bcol] = rb1.x; Bs[bkc + 5][bcol] = rb1.y;
            Bs[bkc + 6][bcol] = rb1.z; Bs[bkc + 7][bcol] = rb1.w;
        } else {
            *(float4*)&Bs[bkk][bnc]     = rb0;
            *(float4*)&Bs[bkk][bnc + 4] = rb1;
        }
        __syncthreads();

        const int kn = k0 + 16;
        const bool more = kn < K;
        if (more) {   // prefetch next tile into regs while computing
            if (ALOAD == 0) {
                ra0 = aok ? *(const float4*)(Ap + kn) : Z;
                ra1 = aok ? *(const float4*)(Ap + kn + 4) : Z;
            } else {
                ra0 = *(const float4*)(Ap + (size_t)kn * lda);
                ra1 = *(const float4*)(Ap + (size_t)kn * lda + lda);
            }
            if (BLOAD == 0) {
                rb0 = bok ? *(const float4*)(Bp + kn) : Z;
                rb1 = bok ? *(const float4*)(Bp + kn + 4) : Z;
            } else {
                rb0 = bok ? *(const float4*)(Bp + (size_t)kn * ldb) : Z;
                rb1 = bok ? *(const float4*)(Bp + (size_t)kn * ldb + 4) : Z;
            }
        }

        // ---- compute 16 k-slices ----
#pragma unroll
        for (int kk = 0; kk < 16; kk++) {
            ulonglong2 qa0 = *(const ulonglong2*)&AsD[kk][2 * rowb];
            ulonglong2 qa1 = *(const ulonglong2*)&AsD[kk][2 * rowb + 4];
            ulonglong2 qa2 = *(const ulonglong2*)&AsD[kk][2 * rowb + 8];
            ulonglong2 qa3 = *(const ulonglong2*)&AsD[kk][2 * rowb + 12];
            ulonglong2 qb0 = *(const ulonglong2*)&Bs[kk][colb];
            ulonglong2 qb1 = *(const ulonglong2*)&Bs[kk][colb + 4];
            ull a[8] = {qa0.x, qa0.y, qa1.x, qa1.y, qa2.x, qa2.y, qa3.x, qa3.y};
            ull b[4] = {qb0.x, qb0.y, qb1.x, qb1.y};
#pragma unroll
            for (int i = 0; i < 8; i++)
#pragma unroll
                for (int j = 0; j < 4; j++) fma2(acc[i][j], a[i], b[j]);
        }
        if (!more) break;
        k0 = kn;
    }

    // ---- epilogue ----
#pragma unroll
    for (int i = 0; i < 8; i++) {
        const int r = bm + rowb + i;
        if (r >= M) continue;
        float* crow = C + (size_t)r * ldc + bn + colb;
        const float* trow = nullptr;
        if (EPI) trow = addrow + (size_t)(r % TT) * ldc + bn + colb;
#pragma unroll
        for (int jj = 0; jj < 2; jj++) {
            const int c = bn + colb + jj * 4;
            if (c >= Ns) continue;
            float2 p0 = upk(acc[i][2 * jj]);
            float2 p1 = upk(acc[i][2 * jj + 1]);
            float4 v = make_float4(p0.x, p0.y, p1.x, p1.y);
            if (EPI) {
                float4 t4 = *(const float4*)(trow + jj * 4);
                float4 b4 = *(const float4*)(bias + c);
                v.x = fmaxf(v.x + t4.x + b4.x, 0.f);
                v.y = fmaxf(v.y + t4.y + b4.y, 0.f);
                v.z = fmaxf(v.z + t4.z + b4.z, 0.f);
                v.w = fmaxf(v.w + t4.w + b4.w, 0.f);
            }
            *(float4*)(crow + jj * 4) = v;
        }
    }
}

// ============================================================================
// Sinkhorn: exp-domain matrix scaling, E register-resident.
// 4-CTA cluster per batch, 512 threads/CTA, 100 rows/CTA.
// Warp w owns nr = (w<4 ? 7 : 6) rows; lane l owns cols t = 2l + 64j (+1), j=0..4.
// Per iter: row scaling (shfl-reduce), col partials -> smem -> reduce ->
// cluster exchange (double-buffered LC). Padding cols t in [315,320) carry 0.
// ============================================================================
__global__ void __cluster_dims__(4, 1, 1) __launch_bounds__(512, 1)
sinkhorn_kernel(float* __restrict__ s, const float* __restrict__ gamma_p,
                const float* __restrict__ beta_p)
{
    __shared__ __align__(16) float CP[16][328];
    __shared__ __align__(16) float LC[2][320];
    __shared__ __align__(16) float Cv[320];
    __shared__ __align__(16) float RED[32];
    __shared__ __align__(16) float ST[8];

    cg::cluster_group cluster = cg::this_cluster();
    const int tid = threadIdx.x, w = tid >> 5, l = tid & 31;
    const int crank = (int)cluster.block_rank();
    const int batch = blockIdx.x >> 2;
    const int nr = (w < 4) ? 7 : 6;
    const int rbase = w * 6 + ((w < 4) ? w : 4);
    float* gbase = s + (size_t)batch * NN_ * TP + (size_t)(crank * 100 + rbase) * TP;

    ull E2[7][5];
    // ---- load + stats (padding cols are 0 -> harmless in sums) ----
    float psum = 0.f, psq = 0.f;
#pragma unroll
    for (int r = 0; r < 7; r++) {
        if (r < nr) {
            const float* rp = gbase + r * TP;
#pragma unroll
            for (int j = 0; j < 5; j++) {
                const int t0 = 2 * l + 64 * j;
                float2 v = *(const float2*)(rp + t0);
                E2[r][j] = pack2(v.x, v.y);
                psum += v.x + v.y;
                psq  += v.x * v.x + v.y * v.y;
            }
        } else {
#pragma unroll
            for (int j = 0; j < 5; j++) E2[r][j] = 0ull;
        }
    }
#pragma unroll
    for (int o = 16; o; o >>= 1) {
        psum += __shfl_xor_sync(0xffffffffu, psum, o);
        psq  += __shfl_xor_sync(0xffffffffu, psq,  o);
    }
    if (l == 0) { RED[w] = psum; RED[16 + w] = psq; }
    __syncthreads();
    if (w == 0) {
        float a = (l < 16) ? RED[l] : 0.f;
        float b = (l < 16) ? RED[16 + l] : 0.f;
#pragma unroll
        for (int o = 8; o; o >>= 1) {
            a += __shfl_xor_sync(0xffffffffu, a, o);
            b += __shfl_xor_sync(0xffffffffu, b, o);
        }
        if (l == 0) { ST[0] = a; ST[1] = b; }
    }
    cluster.sync();
    if (tid == 0) {
        float S = 0.f, Q = 0.f;
#pragma unroll
        for (int c = 0; c < 4; c++) {
            const float* r = (const float*)cluster.map_shared_rank((void*)ST, c);
            S += r[0]; Q += r[1];
        }
        const float inv = 1.0f / (float)(NN_ * TT);
        float m = S * inv;
        float var = Q * inv - m * m;
        float istd = rsqrtf(var + 1e-5f);
        ST[2] = m;
        ST[3] = gamma_p[0] * istd;
        ST[4] = beta_p[0];
    }
    __syncthreads();
    const float mean = ST[2], gi = ST[3], bta = ST[4];

    // ---- E = exp(norm(s)), zero padding cols ----
#pragma unroll
    for (int r = 0; r < 7; r++) {
        if (r < nr) {
#pragma unroll
            for (int j = 0; j < 5; j++) {
                const int t0 = 2 * l + 64 * j;
                float2 v = upk(E2[r][j]);
                float ex = (t0     < TT) ? expf(fmaf(v.x - mean, gi, bta)) : 0.f;
                float ey = (t0 + 1 < TT) ? expf(fmaf(v.y - mean, gi, bta)) : 0.f;
                E2[r][j] = pack2(ex, ey);
            }
        }
    }
    if (tid < 320) Cv[tid] = (tid < TT) ? 1.0f : 0.f;
    __syncthreads();

    float ru[7];
#pragma unroll
    for (int r = 0; r < 7; r++) ru[r] = 0.f;

    // ---- 100 iterations ----
    for (int k = 0; k < 100; k++) {
        ull cv2[5];
#pragma unroll
        for (int j = 0; j < 5; j++) cv2[j] = *(const ull*)&Cv[2 * l + 64 * j];
        // row pass
#pragma unroll
        for (int r = 0; r < 7; r++) {
            if (r < nr) {
                ull a2 = 0ull;
#pragma unroll
                for (int j = 0; j < 5; j++) fma2(a2, E2[r][j], cv2[j]);
                float2 p = upk(a2);
                float a = p.x + p.y;
#pragma unroll
                for (int o = 16; o; o >>= 1) a += __shfl_xor_sync(0xffffffffu, a, o);
                ru[r] = 1.0f / a;
            }
        }
        // col partials over own rows
        ull cp2[5] = {0ull, 0ull, 0ull, 0ull, 0ull};
#pragma unroll
        for (int r = 0; r < 7; r++) {
            if (r < nr) {
                ull rr = dup2(ru[r]);
#pragma unroll
                for (int j = 0; j < 5; j++) fma2(cp2[j], E2[r][j], rr);
            }
        }
#pragma unroll
        for (int j = 0; j < 5; j++) *(ull*)&CP[w][2 * l + 64 * j] = cp2[j];
        __syncthreads();
        const int buf = k & 1;
        if (tid < 320) {
            float tot = 0.f;
#pragma unroll
            for (int ww = 0; ww < 16; ww++) tot += CP[ww][tid];
            LC[buf][tid] = tot;
        }
        cluster.sync();
        if (tid < 320) {
            float tt = 0.f;
#pragma unroll
            for (int c = 0; c < 4; c++) {
                const float* rl = (const float*)cluster.map_shared_rank((void*)&LC[0][0], c);
                tt += rl[buf * 320 + tid];
            }
            Cv[tid] = (tid < TT) ? 1.0f / tt : 0.f;
        }
        __syncthreads();
    }

    // ---- write s1 = E * ru * cv ----
    ull cv2[5];
#pragma unroll
    for (int j = 0; j < 5; j++) cv2[j] = *(const ull*)&Cv[2 * l + 64 * j];
#pragma unroll
    for (int r = 0; r < 7; r++) {
        if (r < nr) {
            const float rr = ru[r];
            float* rp = gbase + r * TP;
#pragma unroll
            for (int j = 0; j < 5; j++) {
                float2 e = upk(E2[r][j]);
                float2 c = upk(cv2[j]);
                *(float2*)(rp + 2 * l + 64 * j) = make_float2(e.x * rr * c.x, e.y * rr * c.y);
            }
        }
    }
    cluster.sync();   // keep SMEM alive until all remote LC reads are done
}

// ============================================================================
// head: pred[i] = h[i,:] @ Wo + bo   (one warp per output row)
// ============================================================================
__global__ void head_kernel(const float* __restrict__ h, const float* __restrict__ Wo,
                            const float* __restrict__ bo, float* __restrict__ out, int total) {
    int gwarp = (blockIdx.x * blockDim.x + threadIdx.x) >> 5;
    int lane = threadIdx.x & 31;
    if (gwarp >= total) return;
    const float* hp = h + (size_t)gwarp * HH;
    float acc = 0.f;
#pragma unroll
    for (int i = lane; i < HH; i += 32) acc += hp[i] * Wo[i];
#pragma unroll
    for (int o = 16; o; o >>= 1) acc += __shfl_xor_sync(0xffffffffu, acc, o);
    if (lane == 0) out[gwarp] = acc + bo[0];
}

// ============================================================================
extern "C" void kernel_launch(void* const* d_in, const int* in_sizes, int n_in,
                              void* d_out, int out_size) {
    (void)in_sizes; (void)n_in; (void)out_size;
    const float* features = (const float*)d_in[0];   // [B, N, D]
    const float* text     = (const float*)d_in[1];   // [T, D]
    const float* Amat     = (const float*)d_in[2];   // [D, D]
    const float* gamma    = (const float*)d_in[3];
    const float* beta     = (const float*)d_in[4];
    const float* Wh       = (const float*)d_in[5];   // [2D, H]
    const float* bh       = (const float*)d_in[6];   // [H]
    const float* Wo       = (const float*)d_in[7];   // [H, 1]
    const float* bo       = (const float*)d_in[8];   // [1]
    float* out = (float*)d_out;                      // [B, T]

    float *tA, *sbuf, *f1, *th, *hbuf;
    cudaGetSymbolAddress((void**)&tA,   g_tA);
    cudaGetSymbolAddress((void**)&sbuf, g_s);
    cudaGetSymbolAddress((void**)&f1,   g_f1);
    cudaGetSymbolAddress((void**)&th,   g_th);
    cudaGetSymbolAddress((void**)&hbuf, g_h);

    dim3 b256(256);

    // tA[t,d] = sum_e text[t,e] * A[d,e]      (NT, M=315 N=512 K=512)
    gemm128<0, 0, 0><<<dim3(3, 4, 1), b256>>>(
        text, Amat, tA, TT, DD, DD, DD, DD, DD, DD, 0, 0, 0, nullptr, nullptr);

    // s[b*n, t] = features @ tA^T             (NT, M=12800 N=315 K=512, ldc=TP, pad stored 0)
    gemm128<0, 0, 0><<<dim3(100, 3, 1), b256>>>(
        features, tA, sbuf, BB * NN_, TT, DD, DD, DD, TP, TP, 0, 0, 0, nullptr, nullptr);

    // instance-norm + 100 sinkhorn iterations, in place
    sinkhorn_kernel<<<BB * 4, 512>>>(sbuf, gamma, beta);

    // features1[b,t,d] = sum_n s1[b,n,t] * features[b,n,d]   (TN, batched)
    gemm128<1, 1, 0><<<dim3(3, 4, BB), b256>>>(
        sbuf, features, f1, TT, DD, NN_, TP, DD, DD, DD,
        (long long)NN_ * TP, (long long)NN_ * DD, (long long)TT * DD, nullptr, nullptr);

    // th[t,h] = text @ Wh_bottom              (NN, M=315 N=256 K=512)
    gemm128<0, 1, 0><<<dim3(3, 2, 1), b256>>>(
        text, Wh + (size_t)DD * HH, th, TT, HH, DD, DD, HH, HH, HH, 0, 0, 0, nullptr, nullptr);

    // h = relu(f1 @ Wh_top + th + bh)         (NN + epilogue, M=10080 N=256 K=512)
    gemm128<0, 1, 1><<<dim3(79, 2, 1), b256>>>(
        f1, Wh, hbuf, BB * TT, HH, DD, DD, HH, HH, HH, 0, 0, 0, th, bh);

    // pred = h @ Wo + bo
    head_kernel<<<(BB * TT * 32 + 255) / 256, 256>>>(hbuf, Wo, bo, out, BB * TT);
}

// round 10
// speedup vs baseline: 1.0465x; 1.0465x over previous
#include <cuda_runtime.h>
#include <cooperative_groups.h>
#include <math.h>

namespace cg = cooperative_groups;
typedef unsigned long long ull;

#define BB   32
#define NN_  400
#define TT   315
#define TP   320      // padded T (row stride of s)
#define DD   512
#define HH   256

// ---------------- scratch (static device globals; no allocations) ----------------
__device__ float g_tA[TT * DD];                 // text @ A^T            [T, D]
__device__ float g_s [BB * NN_ * TP + 128];     // affinity / s1 (padded rows) + over-read pad
__device__ float g_f1[BB * TT * DD];            // mixed features        [B, T, D]
__device__ float g_th[TT * HH];                 // text @ Wh_bottom      [T, H]
__device__ float g_h [BB * TT * HH];            // hidden                [B*T, H]

// ---------------- f32x2 helpers ----------------
__device__ __forceinline__ void fma2(ull& d, ull a, ull b) {
    asm("fma.rn.f32x2 %0, %1, %2, %0;" : "+l"(d) : "l"(a), "l"(b));
}
__device__ __forceinline__ ull dup2(float x) {
    ull r; unsigned u = __float_as_uint(x);
    asm("mov.b64 %0, {%1, %1};" : "=l"(r) : "r"(u));
    return r;
}
__device__ __forceinline__ ull pack2(float x, float y) {
    ull r;
    asm("mov.b64 %0, {%1, %2};" : "=l"(r) : "r"(__float_as_uint(x)), "r"(__float_as_uint(y)));
    return r;
}
__device__ __forceinline__ float2 upk(ull v) {
    float2 f; asm("mov.b64 {%0, %1}, %2;" : "=f"(f.x), "=f"(f.y) : "l"(v));
    return f;
}

// ============================================================================
// 128x64 GEMM, BK=16, 256 threads, 8x4 micro-tile, fma.rn.f32x2.
// Small tile keeps regs ~80 -> no spills, 3 CTAs/SM.
// ALOAD: 0 = A[M,K] row-major k-contig; 1 = A[K,M] m-contig (k-major)
// BLOAD: 0 = NT: B[N,K] k-contig;      1 = NN: B[K,N] n-contig
// EPI:   0 = plain store; 1 = relu(C + addrow[(m%TT)*ldc + n] + bias[n])
// A-tile stored DUPLICATED in smem: AsD[kk][2m]=AsD[kk][2m+1]=a(m,kk).
// ============================================================================
template<int ALOAD, int BLOAD, int EPI>
__global__ __launch_bounds__(256, 3)
void gemm128(const float* __restrict__ A, const float* __restrict__ B, float* __restrict__ C,
             int M, int Nvalid, int K, int lda, int ldb, int ldc, int Ns,
             long long sA, long long sB, long long sC,
             const float* __restrict__ addrow, const float* __restrict__ bias)
{
    __shared__ __align__(16) float AsD[16][264];   // 128 rows duplicated (256) + pad
    __shared__ __align__(16) float Bs[16][68];     // 64 cols + pad

    A += (long long)blockIdx.z * sA;
    B += (long long)blockIdx.z * sB;
    C += (long long)blockIdx.z * sC;

    const int bm = blockIdx.x * 128, bn = blockIdx.y * 64;
    const int tid = threadIdx.x;
    const int tm = tid >> 4, tn = tid & 15;
    const int rowb = tm * 8;      // thread's 8 output rows
    const int colb = tn * 4;      // thread's 4 output cols

    ull acc[8][2];
#pragma unroll
    for (int i = 0; i < 8; i++) { acc[i][0] = 0ull; acc[i][1] = 0ull; }

    // ---- loader index setup ----
    int arow = 0, akc = 0, akk2 = 0, am4 = 0;
    const float* Ap;
    bool aok = true;
    if (ALOAD == 0) {
        arow = tid & 127; akc = (tid >> 7) << 3;
        aok = (bm + arow) < M;
        Ap = A + (size_t)(bm + arow) * lda + akc;
    } else {
        akk2 = tid >> 5; am4 = (tid & 31) << 2;
        Ap = A + (size_t)(akk2 * 2) * lda + bm + am4;
    }
    int bcol = 0, bkc = 0, bkk = 0, bnc = 0;
    const float* Bp;
    bool bok = true;
    if (BLOAD == 0) {
        bcol = tid & 63; bkc = (tid >> 6) << 2;
        bok = (bn + bcol) < Nvalid;
        Bp = B + (size_t)(bn + bcol) * ldb + bkc;
    } else {
        bkk = tid >> 4; bnc = (tid & 15) << 2;
        bok = (bn + bnc) < Nvalid;
        Bp = B + (size_t)bkk * ldb + bn + bnc;
    }

    const float4 Z = make_float4(0.f, 0.f, 0.f, 0.f);
    float4 ra0, ra1, rb0;

    // initial tile load (k0 = 0)
    if (ALOAD == 0) {
        ra0 = aok ? *(const float4*)(Ap) : Z;
        ra1 = aok ? *(const float4*)(Ap + 4) : Z;
    } else {
        ra0 = *(const float4*)(Ap);
        ra1 = *(const float4*)(Ap + lda);
    }
    rb0 = bok ? *(const float4*)(Bp) : Z;

    for (int k0 = 0;;) {
        __syncthreads();
        // ---- store staged tile to smem ----
        if (ALOAD == 0) {
            *(ull*)&AsD[akc + 0][2 * arow] = dup2(ra0.x);
            *(ull*)&AsD[akc + 1][2 * arow] = dup2(ra0.y);
            *(ull*)&AsD[akc + 2][2 * arow] = dup2(ra0.z);
            *(ull*)&AsD[akc + 3][2 * arow] = dup2(ra0.w);
            *(ull*)&AsD[akc + 4][2 * arow] = dup2(ra1.x);
            *(ull*)&AsD[akc + 5][2 * arow] = dup2(ra1.y);
            *(ull*)&AsD[akc + 6][2 * arow] = dup2(ra1.z);
            *(ull*)&AsD[akc + 7][2 * arow] = dup2(ra1.w);
        } else {
            *(float4*)&AsD[akk2 * 2][2 * am4]         = make_float4(ra0.x, ra0.x, ra0.y, ra0.y);
            *(float4*)&AsD[akk2 * 2][2 * am4 + 4]     = make_float4(ra0.z, ra0.z, ra0.w, ra0.w);
            *(float4*)&AsD[akk2 * 2 + 1][2 * am4]     = make_float4(ra1.x, ra1.x, ra1.y, ra1.y);
            *(float4*)&AsD[akk2 * 2 + 1][2 * am4 + 4] = make_float4(ra1.z, ra1.z, ra1.w, ra1.w);
        }
        if (BLOAD == 0) {
            Bs[bkc + 0][bcol] = rb0.x; Bs[bkc + 1][bcol] = rb0.y;
            Bs[bkc + 2][bcol] = rb0.z; Bs[bkc + 3][bcol] = rb0.w;
        } else {
            *(float4*)&Bs[bkk][bnc] = rb0;
        }
        __syncthreads();

        const int kn = k0 + 16;
        const bool more = kn < K;
        if (more) {   // prefetch next tile into regs while computing
            if (ALOAD == 0) {
                ra0 = aok ? *(const float4*)(Ap + kn) : Z;
                ra1 = aok ? *(const float4*)(Ap + kn + 4) : Z;
            } else {
                ra0 = *(const float4*)(Ap + (size_t)kn * lda);
                ra1 = *(const float4*)(Ap + (size_t)kn * lda + lda);
            }
            if (BLOAD == 0) {
                rb0 = bok ? *(const float4*)(Bp + kn) : Z;
            } else {
                rb0 = bok ? *(const float4*)(Bp + (size_t)kn * ldb) : Z;
            }
        }

        // ---- compute 16 k-slices: 16 FFMA2 + 5 LDS.128 per slice ----
#pragma unroll
        for (int kk = 0; kk < 16; kk++) {
            ulonglong2 qa0 = *(const ulonglong2*)&AsD[kk][2 * rowb];
            ulonglong2 qa1 = *(const ulonglong2*)&AsD[kk][2 * rowb + 4];
            ulonglong2 qa2 = *(const ulonglong2*)&AsD[kk][2 * rowb + 8];
            ulonglong2 qa3 = *(const ulonglong2*)&AsD[kk][2 * rowb + 12];
            ulonglong2 qb  = *(const ulonglong2*)&Bs[kk][colb];
            fma2(acc[0][0], qa0.x, qb.x); fma2(acc[0][1], qa0.x, qb.y);
            fma2(acc[1][0], qa0.y, qb.x); fma2(acc[1][1], qa0.y, qb.y);
            fma2(acc[2][0], qa1.x, qb.x); fma2(acc[2][1], qa1.x, qb.y);
            fma2(acc[3][0], qa1.y, qb.x); fma2(acc[3][1], qa1.y, qb.y);
            fma2(acc[4][0], qa2.x, qb.x); fma2(acc[4][1], qa2.x, qb.y);
            fma2(acc[5][0], qa2.y, qb.x); fma2(acc[5][1], qa2.y, qb.y);
            fma2(acc[6][0], qa3.x, qb.x); fma2(acc[6][1], qa3.x, qb.y);
            fma2(acc[7][0], qa3.y, qb.x); fma2(acc[7][1], qa3.y, qb.y);
        }
        if (!more) break;
        k0 = kn;
    }

    // ---- epilogue ----
    const int c = bn + colb;
    if (c < Ns) {
#pragma unroll
        for (int i = 0; i < 8; i++) {
            const int r = bm + rowb + i;
            if (r >= M) continue;
            float2 p0 = upk(acc[i][0]);
            float2 p1 = upk(acc[i][1]);
            float4 v = make_float4(p0.x, p0.y, p1.x, p1.y);
            if (EPI) {
                const float* trow = addrow + (size_t)(r % TT) * ldc + c;
                float4 t4 = *(const float4*)(trow);
                float4 b4 = *(const float4*)(bias + c);
                v.x = fmaxf(v.x + t4.x + b4.x, 0.f);
                v.y = fmaxf(v.y + t4.y + b4.y, 0.f);
                v.z = fmaxf(v.z + t4.z + b4.z, 0.f);
                v.w = fmaxf(v.w + t4.w + b4.w, 0.f);
            }
            *(float4*)(C + (size_t)r * ldc + c) = v;
        }
    }
}

// ============================================================================
// Sinkhorn: exp-domain matrix scaling, E register-resident, EARLY EXIT.
// 4-CTA cluster per batch, 512 threads/CTA, 100 rows/CTA.
// Cv is bit-identical across the 4 CTAs of a cluster (same summed exchange,
// same order), so each CTA independently tests convergence and all break at
// the same iteration. Exit when max |dCv/Cv| <= 4e-7 (fp32 roundoff level).
// ============================================================================
__global__ void __cluster_dims__(4, 1, 1) __launch_bounds__(512, 1)
sinkhorn_kernel(float* __restrict__ s, const float* __restrict__ gamma_p,
                const float* __restrict__ beta_p)
{
    __shared__ __align__(16) float CP[16][328];
    __shared__ __align__(16) float LC[2][320];
    __shared__ __align__(16) float Cv[320];
    __shared__ __align__(16) float RED[32];
    __shared__ __align__(16) float ST[8];
    __shared__ int NC;

    cg::cluster_group cluster = cg::this_cluster();
    const int tid = threadIdx.x, w = tid >> 5, l = tid & 31;
    const int crank = (int)cluster.block_rank();
    const int batch = blockIdx.x >> 2;
    const int nr = (w < 4) ? 7 : 6;
    const int rbase = w * 6 + ((w < 4) ? w : 4);
    float* gbase = s + (size_t)batch * NN_ * TP + (size_t)(crank * 100 + rbase) * TP;

    ull E2[7][5];
    // ---- load + stats (padding cols are 0 -> harmless in sums) ----
    float psum = 0.f, psq = 0.f;
#pragma unroll
    for (int r = 0; r < 7; r++) {
        if (r < nr) {
            const float* rp = gbase + r * TP;
#pragma unroll
            for (int j = 0; j < 5; j++) {
                const int t0 = 2 * l + 64 * j;
                float2 v = *(const float2*)(rp + t0);
                E2[r][j] = pack2(v.x, v.y);
                psum += v.x + v.y;
                psq  += v.x * v.x + v.y * v.y;
            }
        } else {
#pragma unroll
            for (int j = 0; j < 5; j++) E2[r][j] = 0ull;
        }
    }
#pragma unroll
    for (int o = 16; o; o >>= 1) {
        psum += __shfl_xor_sync(0xffffffffu, psum, o);
        psq  += __shfl_xor_sync(0xffffffffu, psq,  o);
    }
    if (l == 0) { RED[w] = psum; RED[16 + w] = psq; }
    __syncthreads();
    if (w == 0) {
        float a = (l < 16) ? RED[l] : 0.f;
        float b = (l < 16) ? RED[16 + l] : 0.f;
#pragma unroll
        for (int o = 8; o; o >>= 1) {
            a += __shfl_xor_sync(0xffffffffu, a, o);
            b += __shfl_xor_sync(0xffffffffu, b, o);
        }
        if (l == 0) { ST[0] = a; ST[1] = b; }
    }
    cluster.sync();
    if (tid == 0) {
        float S = 0.f, Q = 0.f;
#pragma unroll
        for (int c = 0; c < 4; c++) {
            const float* r = (const float*)cluster.map_shared_rank((void*)ST, c);
            S += r[0]; Q += r[1];
        }
        const float inv = 1.0f / (float)(NN_ * TT);
        float m = S * inv;
        float var = Q * inv - m * m;
        float istd = rsqrtf(var + 1e-5f);
        ST[2] = m;
        ST[3] = gamma_p[0] * istd;
        ST[4] = beta_p[0];
    }
    __syncthreads();
    const float mean = ST[2], gi = ST[3], bta = ST[4];

    // ---- E = exp(norm(s)), zero padding cols ----
#pragma unroll
    for (int r = 0; r < 7; r++) {
        if (r < nr) {
#pragma unroll
            for (int j = 0; j < 5; j++) {
                const int t0 = 2 * l + 64 * j;
                float2 v = upk(E2[r][j]);
                float ex = (t0     < TT) ? expf(fmaf(v.x - mean, gi, bta)) : 0.f;
                float ey = (t0 + 1 < TT) ? expf(fmaf(v.y - mean, gi, bta)) : 0.f;
                E2[r][j] = pack2(ex, ey);
            }
        }
    }
    if (tid < 320) Cv[tid] = (tid < TT) ? 1.0f : 0.f;
    __syncthreads();

    float ru[7];
#pragma unroll
    for (int r = 0; r < 7; r++) ru[r] = 0.f;

    // ---- sinkhorn iterations (early exit, cap 100) ----
    for (int k = 0; k < 100; k++) {
        ull cv2[5];
#pragma unroll
        for (int j = 0; j < 5; j++) cv2[j] = *(const ull*)&Cv[2 * l + 64 * j];
        // row pass
#pragma unroll
        for (int r = 0; r < 7; r++) {
            if (r < nr) {
                ull a2 = 0ull;
#pragma unroll
                for (int j = 0; j < 5; j++) fma2(a2, E2[r][j], cv2[j]);
                float2 p = upk(a2);
                float a = p.x + p.y;
#pragma unroll
                for (int o = 16; o; o >>= 1) a += __shfl_xor_sync(0xffffffffu, a, o);
                ru[r] = 1.0f / a;
            }
        }
        // col partials over own rows
        ull cp2[5] = {0ull, 0ull, 0ull, 0ull, 0ull};
#pragma unroll
        for (int r = 0; r < 7; r++) {
            if (r < nr) {
                ull rr = dup2(ru[r]);
#pragma unroll
                for (int j = 0; j < 5; j++) fma2(cp2[j], E2[r][j], rr);
            }
        }
#pragma unroll
        for (int j = 0; j < 5; j++) *(ull*)&CP[w][2 * l + 64 * j] = cp2[j];
        __syncthreads();
        const int buf = k & 1;
        if (tid < 320) {
            float tot = 0.f;
#pragma unroll
            for (int ww = 0; ww < 16; ww++) tot += CP[ww][tid];
            LC[buf][tid] = tot;
        }
        if (tid == 400) NC = 0;     // reset convergence flag (pre-sync, post previous read)
        cluster.sync();
        if (tid < 320) {
            float tt = 0.f;
#pragma unroll
            for (int c = 0; c < 4; c++) {
                const float* rl = (const float*)cluster.map_shared_rank((void*)&LC[0][0], c);
                tt += rl[buf * 320 + tid];
            }
            float nv = (tid < TT) ? 1.0f / tt : 0.f;
            if (tid < TT) {
                float ov = Cv[tid];
                if (fabsf(nv - ov) > 4e-7f * fabsf(ov)) NC = 1;
            }
            Cv[tid] = nv;
        }
        __syncthreads();
        if (NC == 0) break;        // identical decision in all 4 cluster CTAs
    }

    // ---- write s1 = E * ru * cv ----
    ull cv2[5];
#pragma unroll
    for (int j = 0; j < 5; j++) cv2[j] = *(const ull*)&Cv[2 * l + 64 * j];
#pragma unroll
    for (int r = 0; r < 7; r++) {
        if (r < nr) {
            const float rr = ru[r];
            float* rp = gbase + r * TP;
#pragma unroll
            for (int j = 0; j < 5; j++) {
                float2 e = upk(E2[r][j]);
                float2 c = upk(cv2[j]);
                *(float2*)(rp + 2 * l + 64 * j) = make_float2(e.x * rr * c.x, e.y * rr * c.y);
            }
        }
    }
    cluster.sync();   // keep SMEM alive until all remote LC reads are done
}

// ============================================================================
// head: pred[i] = h[i,:] @ Wo + bo   (one warp per output row)
// ============================================================================
__global__ void head_kernel(const float* __restrict__ h, const float* __restrict__ Wo,
                            const float* __restrict__ bo, float* __restrict__ out, int total) {
    int gwarp = (blockIdx.x * blockDim.x + threadIdx.x) >> 5;
    int lane = threadIdx.x & 31;
    if (gwarp >= total) return;
    const float* hp = h + (size_t)gwarp * HH;
    float acc = 0.f;
#pragma unroll
    for (int i = lane; i < HH; i += 32) acc += hp[i] * Wo[i];
#pragma unroll
    for (int o = 16; o; o >>= 1) acc += __shfl_xor_sync(0xffffffffu, acc, o);
    if (lane == 0) out[gwarp] = acc + bo[0];
}

// ============================================================================
extern "C" void kernel_launch(void* const* d_in, const int* in_sizes, int n_in,
                              void* d_out, int out_size) {
    (void)in_sizes; (void)n_in; (void)out_size;
    const float* features = (const float*)d_in[0];   // [B, N, D]
    const float* text     = (const float*)d_in[1];   // [T, D]
    const float* Amat     = (const float*)d_in[2];   // [D, D]
    const float* gamma    = (const float*)d_in[3];
    const float* beta     = (const float*)d_in[4];
    const float* Wh       = (const float*)d_in[5];   // [2D, H]
    const float* bh       = (const float*)d_in[6];   // [H]
    const float* Wo       = (const float*)d_in[7];   // [H, 1]
    const float* bo       = (const float*)d_in[8];   // [1]
    float* out = (float*)d_out;                      // [B, T]

    float *tA, *sbuf, *f1, *th, *hbuf;
    cudaGetSymbolAddress((void**)&tA,   g_tA);
    cudaGetSymbolAddress((void**)&sbuf, g_s);
    cudaGetSymbolAddress((void**)&f1,   g_f1);
    cudaGetSymbolAddress((void**)&th,   g_th);
    cudaGetSymbolAddress((void**)&hbuf, g_h);

    dim3 b256(256);

    // tA[t,d] = sum_e text[t,e] * A[d,e]      (NT, M=315 N=512 K=512)
    gemm128<0, 0, 0><<<dim3(3, 8, 1), b256>>>(
        text, Amat, tA, TT, DD, DD, DD, DD, DD, DD, 0, 0, 0, nullptr, nullptr);

    // s[b*n, t] = features @ tA^T             (NT, M=12800 N=315 K=512, ldc=TP, pad written 0)
    gemm128<0, 0, 0><<<dim3(100, 5, 1), b256>>>(
        features, tA, sbuf, BB * NN_, TT, DD, DD, DD, TP, TP, 0, 0, 0, nullptr, nullptr);

    // instance-norm + sinkhorn (early-exit), in place
    sinkhorn_kernel<<<BB * 4, 512>>>(sbuf, gamma, beta);

    // features1[b,t,d] = sum_n s1[b,n,t] * features[b,n,d]   (TN, batched)
    gemm128<1, 1, 0><<<dim3(3, 8, BB), b256>>>(
        sbuf, features, f1, TT, DD, NN_, TP, DD, DD, DD,
        (long long)NN_ * TP, (long long)NN_ * DD, (long long)TT * DD, nullptr, nullptr);

    // th[t,h] = text @ Wh_bottom              (NN, M=315 N=256 K=512)
    gemm128<0, 1, 0><<<dim3(3, 4, 1), b256>>>(
        text, Wh + (size_t)DD * HH, th, TT, HH, DD, DD, HH, HH, HH, 0, 0, 0, nullptr, nullptr);

    // h = relu(f1 @ Wh_top + th + bh)         (NN + epilogue, M=10080 N=256 K=512)
    gemm128<0, 1, 1><<<dim3(79, 4, 1), b256>>>(
        f1, Wh, hbuf, BB * TT, HH, DD, DD, HH, HH, HH, 0, 0, 0, th, bh);

    // pred = h @ Wo + bo
    head_kernel<<<(BB * TT * 32 + 255) / 256, 256>>>(hbuf, Wo, bo, out, BB * TT);
}

// round 13
// speedup vs baseline: 1.2001x; 1.1468x over previous
#include <cuda_runtime.h>
#include <cooperative_groups.h>
#include <math.h>

namespace cg = cooperative_groups;
typedef unsigned long long ull;

#define BB   32
#define NN_  400
#define TT   315
#define TP   320      // padded T (row stride of s)
#define DD   512
#define HH   256

// ---------------- scratch (static device globals; no allocations) ----------------
__device__ float g_tA[TT * DD];                 // text @ A^T            [T, D]
__device__ float g_s [BB * NN_ * TP + 128];     // affinity / s1 (padded rows) + over-read pad
__device__ float g_f1[BB * TT * DD];            // mixed features        [B, T, D]
__device__ float g_th[TT * HH];                 // text @ Wh_bottom      [T, H]
__device__ float g_h [BB * TT * HH];            // hidden                [B*T, H]

// ---------------- f32x2 helpers (sinkhorn only) ----------------
__device__ __forceinline__ void fma2(ull& d, ull a, ull b) {
    asm("fma.rn.f32x2 %0, %1, %2, %0;" : "+l"(d) : "l"(a), "l"(b));
}
__device__ __forceinline__ ull dup2(float x) {
    ull r; unsigned u = __float_as_uint(x);
    asm("mov.b64 %0, {%1, %1};" : "=l"(r) : "r"(u));
    return r;
}
__device__ __forceinline__ ull pack2(float x, float y) {
    ull r;
    asm("mov.b64 %0, {%1, %2};" : "=l"(r) : "r"(__float_as_uint(x)), "r"(__float_as_uint(y)));
    return r;
}
__device__ __forceinline__ float2 upk(ull v) {
    float2 f; asm("mov.b64 {%0, %1}, %2;" : "=f"(f.x), "=f"(f.y) : "l"(v));
    return f;
}

// ============================================================================
// NT GEMM: C[M,N] = A[M,K](k-contig) * B[N,K](k-contig)^T
// 64x64 tile, BK=16, 256 threads, 4x4/thread. (R1 kernel: measured 33 TF/s.)
// Stores cols [0, Nstore): cols in [Nvalid, Nstore) receive exact zeros
// (B is zero-padded by the okB guard).
// ============================================================================
__global__ void gemm_nt_kernel(const float* __restrict__ A, const float* __restrict__ B,
                               float* __restrict__ C, int M, int Nvalid, int K,
                               int ldc, int Nstore) {
    __shared__ float As[16][65];
    __shared__ float Bs[16][65];
    const int bm = blockIdx.x * 64, bn = blockIdx.y * 64;
    const int tid = threadIdx.x;
    const int tm = tid >> 4, tn = tid & 15;
    const int lr = tid >> 2;            // 0..63
    const int lc = (tid & 3) << 2;      // 0,4,8,12
    const bool okA = (bm + lr) < M;
    const bool okB = (bn + lr) < Nvalid;

    float acc[4][4];
#pragma unroll
    for (int i = 0; i < 4; i++)
#pragma unroll
        for (int j = 0; j < 4; j++) acc[i][j] = 0.f;

    for (int k0 = 0; k0 < K; k0 += 16) {
        float4 av = make_float4(0.f, 0.f, 0.f, 0.f);
        float4 bv = make_float4(0.f, 0.f, 0.f, 0.f);
        if (okA) av = *(const float4*)(A + (size_t)(bm + lr) * K + k0 + lc);
        if (okB) bv = *(const float4*)(B + (size_t)(bn + lr) * K + k0 + lc);
        __syncthreads();
        As[lc + 0][lr] = av.x; As[lc + 1][lr] = av.y; As[lc + 2][lr] = av.z; As[lc + 3][lr] = av.w;
        Bs[lc + 0][lr] = bv.x; Bs[lc + 1][lr] = bv.y; Bs[lc + 2][lr] = bv.z; Bs[lc + 3][lr] = bv.w;
        __syncthreads();
#pragma unroll
        for (int kk = 0; kk < 16; kk++) {
            float a0 = As[kk][tm * 4 + 0], a1 = As[kk][tm * 4 + 1];
            float a2 = As[kk][tm * 4 + 2], a3 = As[kk][tm * 4 + 3];
            float b0 = Bs[kk][tn * 4 + 0], b1 = Bs[kk][tn * 4 + 1];
            float b2 = Bs[kk][tn * 4 + 2], b3 = Bs[kk][tn * 4 + 3];
            acc[0][0] += a0 * b0; acc[0][1] += a0 * b1; acc[0][2] += a0 * b2; acc[0][3] += a0 * b3;
            acc[1][0] += a1 * b0; acc[1][1] += a1 * b1; acc[1][2] += a1 * b2; acc[1][3] += a1 * b3;
            acc[2][0] += a2 * b0; acc[2][1] += a2 * b1; acc[2][2] += a2 * b2; acc[2][3] += a2 * b3;
            acc[3][0] += a3 * b0; acc[3][1] += a3 * b1; acc[3][2] += a3 * b2; acc[3][3] += a3 * b3;
        }
    }
#pragma unroll
    for (int i = 0; i < 4; i++) {
        int r = bm + tm * 4 + i;
        if (r >= M) continue;
#pragma unroll
        for (int j = 0; j < 4; j++) {
            int c = bn + tn * 4 + j;
            if (c < Nstore) C[(size_t)r * ldc + c] = acc[i][j];
        }
    }
}

// ============================================================================
// TN GEMM (batched): C[M,N] = sum_k A[K,M](m-contig) * B[K,N](n-contig)
// (R1 kernel: measured 124 us on the f1 shape.)
// ============================================================================
__global__ void gemm_tn_kernel(const float* __restrict__ A, const float* __restrict__ B,
                               float* __restrict__ C, int M, int N, int K,
                               int lda, int ldb, int ldc,
                               long long sA, long long sB, long long sC) {
    A += (long long)blockIdx.z * sA;
    B += (long long)blockIdx.z * sB;
    C += (long long)blockIdx.z * sC;
    __shared__ float As[16][64];
    __shared__ float Bs[16][64];
    const int bm = blockIdx.x * 64, bn = blockIdx.y * 64;
    const int tid = threadIdx.x;
    const int tm = tid >> 4, tn = tid & 15;
    const int kr = tid >> 4;            // 0..15
    const int nc4 = (tid & 15) << 2;    // 0..60

    float acc[4][4];
#pragma unroll
    for (int i = 0; i < 4; i++)
#pragma unroll
        for (int j = 0; j < 4; j++) acc[i][j] = 0.f;

    for (int k0 = 0; k0 < K; k0 += 16) {
        __syncthreads();
#pragma unroll
        for (int i = 0; i < 4; i++) {
            int e = tid + i * 256;
            int kk = e >> 6, mm = e & 63;
            float v = 0.f;
            if (bm + mm < M) v = A[(size_t)(k0 + kk) * lda + bm + mm];
            As[kk][mm] = v;
        }
        float4 bv = make_float4(0.f, 0.f, 0.f, 0.f);
        if (bn + nc4 < N) bv = *(const float4*)(B + (size_t)(k0 + kr) * ldb + bn + nc4);
        *(float4*)&Bs[kr][nc4] = bv;
        __syncthreads();
#pragma unroll
        for (int kk = 0; kk < 16; kk++) {
            float4 a = *(float4*)&As[kk][tm * 4];
            float4 b = *(float4*)&Bs[kk][tn * 4];
            acc[0][0] += a.x * b.x; acc[0][1] += a.x * b.y; acc[0][2] += a.x * b.z; acc[0][3] += a.x * b.w;
            acc[1][0] += a.y * b.x; acc[1][1] += a.y * b.y; acc[1][2] += a.y * b.z; acc[1][3] += a.y * b.w;
            acc[2][0] += a.z * b.x; acc[2][1] += a.z * b.y; acc[2][2] += a.z * b.z; acc[2][3] += a.z * b.w;
            acc[3][0] += a.w * b.x; acc[3][1] += a.w * b.y; acc[3][2] += a.w * b.z; acc[3][3] += a.w * b.w;
        }
    }
#pragma unroll
    for (int i = 0; i < 4; i++) {
        int r = bm + tm * 4 + i;
        if (r >= M) continue;
#pragma unroll
        for (int j = 0; j < 4; j++) {
            int c = bn + tn * 4 + j;
            if (c < N) C[(size_t)r * ldc + c] = acc[i][j];
        }
    }
}

// ============================================================================
// NN GEMM: C[M,N] = A[M,K](k-contig) * B[K,N](n-contig)
// EPI==1: C = relu(C + addrow[(m % TT)*N + n] + bias[n])
// ============================================================================
template <int EPI>
__global__ void gemm_nn_kernel(const float* __restrict__ A, const float* __restrict__ B,
                               float* __restrict__ C, int M, int N, int K,
                               const float* __restrict__ addrow,
                               const float* __restrict__ bias) {
    __shared__ float As[16][65];
    __shared__ float Bs[16][64];
    const int bm = blockIdx.x * 64, bn = blockIdx.y * 64;
    const int tid = threadIdx.x;
    const int tm = tid >> 4, tn = tid & 15;
    const int lr = tid >> 2;
    const int lc = (tid & 3) << 2;
    const int kr = tid >> 4;
    const int nc4 = (tid & 15) << 2;
    const bool okA = (bm + lr) < M;
    const bool okB = (bn + nc4) < N;

    float acc[4][4];
#pragma unroll
    for (int i = 0; i < 4; i++)
#pragma unroll
        for (int j = 0; j < 4; j++) acc[i][j] = 0.f;

    for (int k0 = 0; k0 < K; k0 += 16) {
        float4 av = make_float4(0.f, 0.f, 0.f, 0.f);
        float4 bv = make_float4(0.f, 0.f, 0.f, 0.f);
        if (okA) av = *(const float4*)(A + (size_t)(bm + lr) * K + k0 + lc);
        if (okB) bv = *(const float4*)(B + (size_t)(k0 + kr) * N + bn + nc4);
        __syncthreads();
        As[lc + 0][lr] = av.x; As[lc + 1][lr] = av.y; As[lc + 2][lr] = av.z; As[lc + 3][lr] = av.w;
        *(float4*)&Bs[kr][nc4] = bv;
        __syncthreads();
#pragma unroll
        for (int kk = 0; kk < 16; kk++) {
            float a0 = As[kk][tm * 4 + 0], a1 = As[kk][tm * 4 + 1];
            float a2 = As[kk][tm * 4 + 2], a3 = As[kk][tm * 4 + 3];
            float4 b = *(float4*)&Bs[kk][tn * 4];
            acc[0][0] += a0 * b.x; acc[0][1] += a0 * b.y; acc[0][2] += a0 * b.z; acc[0][3] += a0 * b.w;
            acc[1][0] += a1 * b.x; acc[1][1] += a1 * b.y; acc[1][2] += a1 * b.z; acc[1][3] += a1 * b.w;
            acc[2][0] += a2 * b.x; acc[2][1] += a2 * b.y; acc[2][2] += a2 * b.z; acc[2][3] += a2 * b.w;
            acc[3][0] += a3 * b.x; acc[3][1] += a3 * b.y; acc[3][2] += a3 * b.z; acc[3][3] += a3 * b.w;
        }
    }
#pragma unroll
    for (int i = 0; i < 4; i++) {
        int r = bm + tm * 4 + i;
        if (r >= M) continue;
        int t = r % TT;
#pragma unroll
        for (int j = 0; j < 4; j++) {
            int c = bn + tn * 4 + j;
            if (c < N) {
                float v = acc[i][j];
                if (EPI) {
                    v += addrow[(size_t)t * N + c] + bias[c];
                    v = fmaxf(v, 0.f);
                }
                C[(size_t)r * N + c] = v;
            }
        }
    }
}

// ============================================================================
// Sinkhorn: exp-domain matrix scaling, E register-resident, EARLY EXIT (1e-5).
// 4-CTA cluster per batch, 512 threads/CTA, 100 rows/CTA.
// Cv is bit-identical across cluster CTAs -> independent, consistent exit.
// ============================================================================
__global__ void __cluster_dims__(4, 1, 1) __launch_bounds__(512, 1)
sinkhorn_kernel(float* __restrict__ s, const float* __restrict__ gamma_p,
                const float* __restrict__ beta_p)
{
    __shared__ __align__(16) float CP[16][328];
    __shared__ __align__(16) float LC[2][320];
    __shared__ __align__(16) float Cv[320];
    __shared__ __align__(16) float RED[32];
    __shared__ __align__(16) float ST[8];
    __shared__ int NC;

    cg::cluster_group cluster = cg::this_cluster();
    const int tid = threadIdx.x, w = tid >> 5, l = tid & 31;
    const int crank = (int)cluster.block_rank();
    const int batch = blockIdx.x >> 2;
    const int nr = (w < 4) ? 7 : 6;
    const int rbase = w * 6 + ((w < 4) ? w : 4);
    float* gbase = s + (size_t)batch * NN_ * TP + (size_t)(crank * 100 + rbase) * TP;

    ull E2[7][5];
    // ---- load + stats (padding cols hold exact zeros from the s-GEMM) ----
    float psum = 0.f, psq = 0.f;
#pragma unroll
    for (int r = 0; r < 7; r++) {
        if (r < nr) {
            const float* rp = gbase + r * TP;
#pragma unroll
            for (int j = 0; j < 5; j++) {
                const int t0 = 2 * l + 64 * j;
                float2 v = *(const float2*)(rp + t0);
                E2[r][j] = pack2(v.x, v.y);
                psum += v.x + v.y;
                psq  += v.x * v.x + v.y * v.y;
            }
        } else {
#pragma unroll
            for (int j = 0; j < 5; j++) E2[r][j] = 0ull;
        }
    }
#pragma unroll
    for (int o = 16; o; o >>= 1) {
        psum += __shfl_xor_sync(0xffffffffu, psum, o);
        psq  += __shfl_xor_sync(0xffffffffu, psq,  o);
    }
    if (l == 0) { RED[w] = psum; RED[16 + w] = psq; }
    __syncthreads();
    if (w == 0) {
        float a = (l < 16) ? RED[l] : 0.f;
        float b = (l < 16) ? RED[16 + l] : 0.f;
#pragma unroll
        for (int o = 8; o; o >>= 1) {
            a += __shfl_xor_sync(0xffffffffu, a, o);
            b += __shfl_xor_sync(0xffffffffu, b, o);
        }
        if (l == 0) { ST[0] = a; ST[1] = b; }
    }
    cluster.sync();
    if (tid == 0) {
        float S = 0.f, Q = 0.f;
#pragma unroll
        for (int c = 0; c < 4; c++) {
            const float* r = (const float*)cluster.map_shared_rank((void*)ST, c);
            S += r[0]; Q += r[1];
        }
        const float inv = 1.0f / (float)(NN_ * TT);
        float m = S * inv;
        float var = Q * inv - m * m;
        float istd = rsqrtf(var + 1e-5f);
        ST[2] = m;
        ST[3] = gamma_p[0] * istd;
        ST[4] = beta_p[0];
    }
    __syncthreads();
    const float mean = ST[2], gi = ST[3], bta = ST[4];

    // ---- E = exp(norm(s)), zero padding cols ----
#pragma unroll
    for (int r = 0; r < 7; r++) {
        if (r < nr) {
#pragma unroll
            for (int j = 0; j < 5; j++) {
                const int t0 = 2 * l + 64 * j;
                float2 v = upk(E2[r][j]);
                float ex = (t0     < TT) ? expf(fmaf(v.x - mean, gi, bta)) : 0.f;
                float ey = (t0 + 1 < TT) ? expf(fmaf(v.y - mean, gi, bta)) : 0.f;
                E2[r][j] = pack2(ex, ey);
            }
        }
    }
    if (tid < 320) Cv[tid] = (tid < TT) ? 1.0f : 0.f;
    __syncthreads();

    float ru[7];
#pragma unroll
    for (int r = 0; r < 7; r++) ru[r] = 0.f;

    // ---- sinkhorn iterations (early exit, cap 100) ----
    for (int k = 0; k < 100; k++) {
        ull cv2[5];
#pragma unroll
        for (int j = 0; j < 5; j++) cv2[j] = *(const ull*)&Cv[2 * l + 64 * j];
        // row pass
#pragma unroll
        for (int r = 0; r < 7; r++) {
            if (r < nr) {
                ull a2 = 0ull;
#pragma unroll
                for (int j = 0; j < 5; j++) fma2(a2, E2[r][j], cv2[j]);
                float2 p = upk(a2);
                float a = p.x + p.y;
#pragma unroll
                for (int o = 16; o; o >>= 1) a += __shfl_xor_sync(0xffffffffu, a, o);
                ru[r] = 1.0f / a;
            }
        }
        // col partials over own rows
        ull cp2[5] = {0ull, 0ull, 0ull, 0ull, 0ull};
#pragma unroll
        for (int r = 0; r < 7; r++) {
            if (r < nr) {
                ull rr = dup2(ru[r]);
#pragma unroll
                for (int j = 0; j < 5; j++) fma2(cp2[j], E2[r][j], rr);
            }
        }
#pragma unroll
        for (int j = 0; j < 5; j++) *(ull*)&CP[w][2 * l + 64 * j] = cp2[j];
        __syncthreads();
        const int buf = k & 1;
        if (tid < 320) {
            float tot = 0.f;
#pragma unroll
            for (int ww = 0; ww < 16; ww++) tot += CP[ww][tid];
            LC[buf][tid] = tot;
        }
        if (tid == 400) NC = 0;
        cluster.sync();
        if (tid < 320) {
            float tt = 0.f;
#pragma unroll
            for (int c = 0; c < 4; c++) {
                const float* rl = (const float*)cluster.map_shared_rank((void*)&LC[0][0], c);
                tt += rl[buf * 320 + tid];
            }
            float nv = (tid < TT) ? 1.0f / tt : 0.f;
            if (tid < TT) {
                float ov = Cv[tid];
                if (fabsf(nv - ov) > 1e-5f * fabsf(ov)) NC = 1;
            }
            Cv[tid] = nv;
        }
        __syncthreads();
        if (NC == 0) break;        // identical decision in all 4 cluster CTAs
    }

    // ---- write s1 = E * ru * cv ----
    ull cv2[5];
#pragma unroll
    for (int j = 0; j < 5; j++) cv2[j] = *(const ull*)&Cv[2 * l + 64 * j];
#pragma unroll
    for (int r = 0; r < 7; r++) {
        if (r < nr) {
            const float rr = ru[r];
            float* rp = gbase + r * TP;
#pragma unroll
            for (int j = 0; j < 5; j++) {
                float2 e = upk(E2[r][j]);
                float2 c = upk(cv2[j]);
                *(float2*)(rp + 2 * l + 64 * j) = make_float2(e.x * rr * c.x, e.y * rr * c.y);
            }
        }
    }
    cluster.sync();   // keep SMEM alive until all remote LC reads are done
}

// ============================================================================
// head: pred[i] = h[i,:] @ Wo + bo   (one warp per output row)
// ============================================================================
__global__ void head_kernel(const float* __restrict__ h, const float* __restrict__ Wo,
                            const float* __restrict__ bo, float* __restrict__ out, int total) {
    int gwarp = (blockIdx.x * blockDim.x + threadIdx.x) >> 5;
    int lane = threadIdx.x & 31;
    if (gwarp >= total) return;
    const float* hp = h + (size_t)gwarp * HH;
    float acc = 0.f;
#pragma unroll
    for (int i = lane; i < HH; i += 32) acc += hp[i] * Wo[i];
#pragma unroll
    for (int o = 16; o; o >>= 1) acc += __shfl_xor_sync(0xffffffffu, acc, o);
    if (lane == 0) out[gwarp] = acc + bo[0];
}

// ============================================================================
extern "C" void kernel_launch(void* const* d_in, const int* in_sizes, int n_in,
                              void* d_out, int out_size) {
    (void)in_sizes; (void)n_in; (void)out_size;
    const float* features = (const float*)d_in[0];   // [B, N, D]
    const float* text     = (const float*)d_in[1];   // [T, D]
    const float* Amat     = (const float*)d_in[2];   // [D, D]
    const float* gamma    = (const float*)d_in[3];
    const float* beta     = (const float*)d_in[4];
    const float* Wh       = (const float*)d_in[5];   // [2D, H]
    const float* bh       = (const float*)d_in[6];   // [H]
    const float* Wo       = (const float*)d_in[7];   // [H, 1]
    const float* bo       = (const float*)d_in[8];   // [1]
    float* out = (float*)d_out;                      // [B, T]

    float *tA, *sbuf, *f1, *th, *hbuf;
    cudaGetSymbolAddress((void**)&tA,   g_tA);
    cudaGetSymbolAddress((void**)&sbuf, g_s);
    cudaGetSymbolAddress((void**)&f1,   g_f1);
    cudaGetSymbolAddress((void**)&th,   g_th);
    cudaGetSymbolAddress((void**)&hbuf, g_h);

    dim3 b256(256);

    // tA[t,d] = sum_e text[t,e] * A[d,e]      (NT, M=315 N=512 K=512)
    gemm_nt_kernel<<<dim3(5, 8), b256>>>(text, Amat, tA, TT, DD, DD, DD, DD);

    // s[b*n, t] = features @ tA^T             (NT, M=12800 N=315 K=512, ldc=TP,
    //                                          cols 315..319 stored as exact zeros)
    gemm_nt_kernel<<<dim3(200, 5), b256>>>(
        features, tA, sbuf, BB * NN_, TT, DD, TP, TP);

    // instance-norm + sinkhorn (early-exit @1e-5), in place
    sinkhorn_kernel<<<BB * 4, 512>>>(sbuf, gamma, beta);

    // features1[b,t,d] = sum_n s1[b,n,t] * features[b,n,d]   (TN, batched)
    gemm_tn_kernel<<<dim3(5, 8, BB), b256>>>(
        sbuf, features, f1, TT, DD, NN_, TP, DD, DD,
        (long long)NN_ * TP, (long long)NN_ * DD, (long long)TT * DD);

    // th[t,h] = text @ Wh_bottom              (NN, M=315 N=256 K=512)
    gemm_nn_kernel<0><<<dim3(5, 4), b256>>>(
        text, Wh + (size_t)DD * HH, th, TT, HH, DD, nullptr, nullptr);

    // h = relu(f1 @ Wh_top + th + bh)         (NN + epilogue, M=10080 N=256 K=512)
    gemm_nn_kernel<1><<<dim3(158, 4), b256>>>(
        f1, Wh, hbuf, BB * TT, HH, DD, th, bh);

    // pred = h @ Wo + bo
    head_kernel<<<(BB * TT * 32 + 255) / 256, 256>>>(hbuf, Wo, bo, out, BB * TT);
}

// round 14
// speedup vs baseline: 1.2096x; 1.0079x over previous
#include <cuda_runtime.h>
#include <cooperative_groups.h>
#include <math.h>

namespace cg = cooperative_groups;
typedef unsigned long long ull;

#define BB   32
#define NN_  400
#define TT   315
#define TP   320      // padded T (row stride of s)
#define DD   512
#define HH   256

// ---------------- scratch (static device globals; no allocations) ----------------
__device__ float g_tA[TT * DD];                 // text @ A^T            [T, D]
__device__ float g_s [BB * NN_ * TP + 128];     // affinity / s1 (padded rows) + over-read pad
__device__ float g_f1[BB * TT * DD];            // mixed features        [B, T, D]
__device__ float g_th[TT * HH];                 // text @ Wh_bottom      [T, H]
__device__ float g_h [BB * TT * HH];            // hidden                [B*T, H]

// ---------------- f32x2 helpers (sinkhorn only) ----------------
__device__ __forceinline__ void fma2(ull& d, ull a, ull b) {
    asm("fma.rn.f32x2 %0, %1, %2, %0;" : "+l"(d) : "l"(a), "l"(b));
}
__device__ __forceinline__ ull dup2(float x) {
    ull r; unsigned u = __float_as_uint(x);
    asm("mov.b64 %0, {%1, %1};" : "=l"(r) : "r"(u));
    return r;
}
__device__ __forceinline__ ull pack2(float x, float y) {
    ull r;
    asm("mov.b64 %0, {%1, %2};" : "=l"(r) : "r"(__float_as_uint(x)), "r"(__float_as_uint(y)));
    return r;
}
__device__ __forceinline__ float2 upk(ull v) {
    float2 f; asm("mov.b64 {%0, %1}, %2;" : "=f"(f.x), "=f"(f.y) : "l"(v));
    return f;
}

// ---------------- cluster / mbarrier helpers ----------------
__device__ __forceinline__ uint32_t s2u(const void* p) {
    return (uint32_t)__cvta_generic_to_shared(p);
}
__device__ __forceinline__ void mbar_init(uint32_t a, int cnt) {
    asm volatile("mbarrier.init.shared.b64 [%0], %1;" :: "r"(a), "r"(cnt));
}
__device__ __forceinline__ uint32_t mapa_u32(uint32_t a, int rank) {
    uint32_t r;
    asm("mapa.shared::cluster.u32 %0, %1, %2;" : "=r"(r) : "r"(a), "r"(rank));
    return r;
}
__device__ __forceinline__ void st_cluster_f32(uint32_t a, float v) {
    asm volatile("st.shared::cluster.f32 [%0], %1;" :: "r"(a), "f"(v) : "memory");
}
__device__ __forceinline__ void fence_cluster() {
    asm volatile("fence.acq_rel.cluster;" ::: "memory");
}
__device__ __forceinline__ void mbar_arrive_cluster(uint32_t a) {
    asm volatile("mbarrier.arrive.shared::cluster.b64 _, [%0];" :: "r"(a) : "memory");
}
__device__ __forceinline__ void mbar_wait_parity(uint32_t a, uint32_t ph) {
    uint32_t done;
    asm volatile(
        "{\n\t.reg .pred p;\n\t"
        "mbarrier.try_wait.parity.acquire.cta.shared::cta.b64 p, [%1], %2;\n\t"
        "selp.b32 %0, 1, 0, p;\n\t}"
        : "=r"(done) : "r"(a), "r"(ph) : "memory");
    if (!done) {
        asm volatile(
            "{\n\t.reg .pred P1;\n\t"
            "WL_%=:\n\t"
            "mbarrier.try_wait.parity.acquire.cta.shared::cta.b64 P1, [%0], %1, 0x989680;\n\t"
            "@P1 bra.uni WD_%=;\n\t"
            "bra.uni WL_%=;\n\t"
            "WD_%=:\n\t}"
            :: "r"(a), "r"(ph) : "memory");
    }
}

// ============================================================================
// NT GEMM: C[M,N] = A[M,K](k-contig) * B[N,K](k-contig)^T
// 64x64 tile, BK=16, 256 threads, 4x4/thread. Measured ~33 TF/s (92% scalar peak).
// Stores cols [0, Nstore): cols in [Nvalid, Nstore) receive exact zeros.
// ============================================================================
__global__ void gemm_nt_kernel(const float* __restrict__ A, const float* __restrict__ B,
                               float* __restrict__ C, int M, int Nvalid, int K,
                               int ldc, int Nstore) {
    __shared__ float As[16][65];
    __shared__ float Bs[16][65];
    const int bm = blockIdx.x * 64, bn = blockIdx.y * 64;
    const int tid = threadIdx.x;
    const int tm = tid >> 4, tn = tid & 15;
    const int lr = tid >> 2;            // 0..63
    const int lc = (tid & 3) << 2;      // 0,4,8,12
    const bool okA = (bm + lr) < M;
    const bool okB = (bn + lr) < Nvalid;

    float acc[4][4];
#pragma unroll
    for (int i = 0; i < 4; i++)
#pragma unroll
        for (int j = 0; j < 4; j++) acc[i][j] = 0.f;

    for (int k0 = 0; k0 < K; k0 += 16) {
        float4 av = make_float4(0.f, 0.f, 0.f, 0.f);
        float4 bv = make_float4(0.f, 0.f, 0.f, 0.f);
        if (okA) av = *(const float4*)(A + (size_t)(bm + lr) * K + k0 + lc);
        if (okB) bv = *(const float4*)(B + (size_t)(bn + lr) * K + k0 + lc);
        __syncthreads();
        As[lc + 0][lr] = av.x; As[lc + 1][lr] = av.y; As[lc + 2][lr] = av.z; As[lc + 3][lr] = av.w;
        Bs[lc + 0][lr] = bv.x; Bs[lc + 1][lr] = bv.y; Bs[lc + 2][lr] = bv.z; Bs[lc + 3][lr] = bv.w;
        __syncthreads();
#pragma unroll
        for (int kk = 0; kk < 16; kk++) {
            float a0 = As[kk][tm * 4 + 0], a1 = As[kk][tm * 4 + 1];
            float a2 = As[kk][tm * 4 + 2], a3 = As[kk][tm * 4 + 3];
            float b0 = Bs[kk][tn * 4 + 0], b1 = Bs[kk][tn * 4 + 1];
            float b2 = Bs[kk][tn * 4 + 2], b3 = Bs[kk][tn * 4 + 3];
            acc[0][0] += a0 * b0; acc[0][1] += a0 * b1; acc[0][2] += a0 * b2; acc[0][3] += a0 * b3;
            acc[1][0] += a1 * b0; acc[1][1] += a1 * b1; acc[1][2] += a1 * b2; acc[1][3] += a1 * b3;
            acc[2][0] += a2 * b0; acc[2][1] += a2 * b1; acc[2][2] += a2 * b2; acc[2][3] += a2 * b3;
            acc[3][0] += a3 * b0; acc[3][1] += a3 * b1; acc[3][2] += a3 * b2; acc[3][3] += a3 * b3;
        }
    }
#pragma unroll
    for (int i = 0; i < 4; i++) {
        int r = bm + tm * 4 + i;
        if (r >= M) continue;
#pragma unroll
        for (int j = 0; j < 4; j++) {
            int c = bn + tn * 4 + j;
            if (c < Nstore) C[(size_t)r * ldc + c] = acc[i][j];
        }
    }
}

// ============================================================================
// TN GEMM (batched): C[M,N] = sum_k A[K,M](m-contig) * B[K,N](n-contig)
// ============================================================================
__global__ void gemm_tn_kernel(const float* __restrict__ A, const float* __restrict__ B,
                               float* __restrict__ C, int M, int N, int K,
                               int lda, int ldb, int ldc,
                               long long sA, long long sB, long long sC) {
    A += (long long)blockIdx.z * sA;
    B += (long long)blockIdx.z * sB;
    C += (long long)blockIdx.z * sC;
    __shared__ float As[16][64];
    __shared__ float Bs[16][64];
    const int bm = blockIdx.x * 64, bn = blockIdx.y * 64;
    const int tid = threadIdx.x;
    const int tm = tid >> 4, tn = tid & 15;
    const int kr = tid >> 4;            // 0..15
    const int nc4 = (tid & 15) << 2;    // 0..60

    float acc[4][4];
#pragma unroll
    for (int i = 0; i < 4; i++)
#pragma unroll
        for (int j = 0; j < 4; j++) acc[i][j] = 0.f;

    for (int k0 = 0; k0 < K; k0 += 16) {
        __syncthreads();
#pragma unroll
        for (int i = 0; i < 4; i++) {
            int e = tid + i * 256;
            int kk = e >> 6, mm = e & 63;
            float v = 0.f;
            if (bm + mm < M) v = A[(size_t)(k0 + kk) * lda + bm + mm];
            As[kk][mm] = v;
        }
        float4 bv = make_float4(0.f, 0.f, 0.f, 0.f);
        if (bn + nc4 < N) bv = *(const float4*)(B + (size_t)(k0 + kr) * ldb + bn + nc4);
        *(float4*)&Bs[kr][nc4] = bv;
        __syncthreads();
#pragma unroll
        for (int kk = 0; kk < 16; kk++) {
            float4 a = *(float4*)&As[kk][tm * 4];
            float4 b = *(float4*)&Bs[kk][tn * 4];
            acc[0][0] += a.x * b.x; acc[0][1] += a.x * b.y; acc[0][2] += a.x * b.z; acc[0][3] += a.x * b.w;
            acc[1][0] += a.y * b.x; acc[1][1] += a.y * b.y; acc[1][2] += a.y * b.z; acc[1][3] += a.y * b.w;
            acc[2][0] += a.z * b.x; acc[2][1] += a.z * b.y; acc[2][2] += a.z * b.z; acc[2][3] += a.z * b.w;
            acc[3][0] += a.w * b.x; acc[3][1] += a.w * b.y; acc[3][2] += a.w * b.z; acc[3][3] += a.w * b.w;
        }
    }
#pragma unroll
    for (int i = 0; i < 4; i++) {
        int r = bm + tm * 4 + i;
        if (r >= M) continue;
#pragma unroll
        for (int j = 0; j < 4; j++) {
            int c = bn + tn * 4 + j;
            if (c < N) C[(size_t)r * ldc + c] = acc[i][j];
        }
    }
}

// ============================================================================
// NN GEMM: C[M,N] = A[M,K](k-contig) * B[K,N](n-contig)
// EPI==1: C = relu(C + addrow[(m % TT)*N + n] + bias[n])
// ============================================================================
template <int EPI>
__global__ void gemm_nn_kernel(const float* __restrict__ A, const float* __restrict__ B,
                               float* __restrict__ C, int M, int N, int K,
                               const float* __restrict__ addrow,
                               const float* __restrict__ bias) {
    __shared__ float As[16][65];
    __shared__ float Bs[16][64];
    const int bm = blockIdx.x * 64, bn = blockIdx.y * 64;
    const int tid = threadIdx.x;
    const int tm = tid >> 4, tn = tid & 15;
    const int lr = tid >> 2;
    const int lc = (tid & 3) << 2;
    const int kr = tid >> 4;
    const int nc4 = (tid & 15) << 2;
    const bool okA = (bm + lr) < M;
    const bool okB = (bn + nc4) < N;

    float acc[4][4];
#pragma unroll
    for (int i = 0; i < 4; i++)
#pragma unroll
        for (int j = 0; j < 4; j++) acc[i][j] = 0.f;

    for (int k0 = 0; k0 < K; k0 += 16) {
        float4 av = make_float4(0.f, 0.f, 0.f, 0.f);
        float4 bv = make_float4(0.f, 0.f, 0.f, 0.f);
        if (okA) av = *(const float4*)(A + (size_t)(bm + lr) * K + k0 + lc);
        if (okB) bv = *(const float4*)(B + (size_t)(k0 + kr) * N + bn + nc4);
        __syncthreads();
        As[lc + 0][lr] = av.x; As[lc + 1][lr] = av.y; As[lc + 2][lr] = av.z; As[lc + 3][lr] = av.w;
        *(float4*)&Bs[kr][nc4] = bv;
        __syncthreads();
#pragma unroll
        for (int kk = 0; kk < 16; kk++) {
            float a0 = As[kk][tm * 4 + 0], a1 = As[kk][tm * 4 + 1];
            float a2 = As[kk][tm * 4 + 2], a3 = As[kk][tm * 4 + 3];
            float4 b = *(float4*)&Bs[kk][tn * 4];
            acc[0][0] += a0 * b.x; acc[0][1] += a0 * b.y; acc[0][2] += a0 * b.z; acc[0][3] += a0 * b.w;
            acc[1][0] += a1 * b.x; acc[1][1] += a1 * b.y; acc[1][2] += a1 * b.z; acc[1][3] += a1 * b.w;
            acc[2][0] += a2 * b.x; acc[2][1] += a2 * b.y; acc[2][2] += a2 * b.z; acc[2][3] += a2 * b.w;
            acc[3][0] += a3 * b.x; acc[3][1] += a3 * b.y; acc[3][2] += a3 * b.z; acc[3][3] += a3 * b.w;
        }
    }
#pragma unroll
    for (int i = 0; i < 4; i++) {
        int r = bm + tm * 4 + i;
        if (r >= M) continue;
        int t = r % TT;
#pragma unroll
        for (int j = 0; j < 4; j++) {
            int c = bn + tn * 4 + j;
            if (c < N) {
                float v = acc[i][j];
                if (EPI) {
                    v += addrow[(size_t)t * N + c] + bias[c];
                    v = fmaxf(v, 0.f);
                }
                C[(size_t)r * N + c] = v;
            }
        }
    }
}

// ============================================================================
// Sinkhorn v2: exp-domain matrix scaling, E register-resident.
// 4-CTA cluster per batch, 640 threads/CTA (20 warps x 5 rows), 100 rows/CTA.
// Per-iteration cluster exchange is PUSH-based (st.shared::cluster into the
// other 3 CTAs' RCV slots + mbarrier), replacing cluster.sync (+CCTL.IVALL)
// and serialized remote reads. Cv summed in rank order -> bit-identical across
// CTAs -> consistent early-exit decision. Double-buffered RCV/mbar/NC.
// ============================================================================
__global__ void __cluster_dims__(4, 1, 1) __launch_bounds__(640, 1)
sinkhorn_kernel(float* __restrict__ s, const float* __restrict__ gamma_p,
                const float* __restrict__ beta_p)
{
    __shared__ __align__(16) float CP[20][324];
    __shared__ __align__(16) float RCV[2][4][320];
    __shared__ __align__(16) float Cv[320];
    __shared__ __align__(16) float RED[48];
    __shared__ __align__(16) float ST[8];
    __shared__ __align__(8)  ull   MBAR[2];
    __shared__ int NC2[2];

    cg::cluster_group cluster = cg::this_cluster();
    const int tid = threadIdx.x, w = tid >> 5, l = tid & 31;
    const int crank = (int)cluster.block_rank();
    const int batch = blockIdx.x >> 2;
    const int rbase = w * 5;                       // 5 rows per warp, 20 warps
    float* gbase = s + (size_t)batch * NN_ * TP + (size_t)(crank * 100 + rbase) * TP;

    const uint32_t mb_u32  = s2u(&MBAR[0]);
    const uint32_t rcv_u32 = s2u(&RCV[0][0][0]);
    if (tid == 0) {
        mbar_init(mb_u32, 3);          // 3 remote arrivals per iteration
        mbar_init(mb_u32 + 8, 3);
        NC2[0] = 1; NC2[1] = 1;
    }
    // remote base addresses for the 3 peer CTAs (rank order preserved in slots)
    uint32_t r_rcv[3], r_mb[3];
#pragma unroll
    for (int i = 0; i < 3; i++) {
        const int c = i + (i >= crank ? 1 : 0);
        r_rcv[i] = mapa_u32(rcv_u32, c);
        r_mb[i]  = mapa_u32(mb_u32, c);
    }

    ull E2[5][5];
    // ---- load + stats (padding cols hold exact zeros from the s-GEMM) ----
    float psum = 0.f, psq = 0.f;
#pragma unroll
    for (int r = 0; r < 5; r++) {
        const float* rp = gbase + r * TP;
#pragma unroll
        for (int j = 0; j < 5; j++) {
            const int t0 = 2 * l + 64 * j;
            float2 v = *(const float2*)(rp + t0);
            E2[r][j] = pack2(v.x, v.y);
            psum += v.x + v.y;
            psq  += v.x * v.x + v.y * v.y;
        }
    }
#pragma unroll
    for (int o = 16; o; o >>= 1) {
        psum += __shfl_xor_sync(0xffffffffu, psum, o);
        psq  += __shfl_xor_sync(0xffffffffu, psq,  o);
    }
    if (l == 0) { RED[w] = psum; RED[24 + w] = psq; }
    __syncthreads();
    if (w == 0) {
        float a = (l < 20) ? RED[l] : 0.f;
        float b = (l < 20) ? RED[24 + l] : 0.f;
#pragma unroll
        for (int o = 16; o; o >>= 1) {
            a += __shfl_xor_sync(0xffffffffu, a, o);
            b += __shfl_xor_sync(0xffffffffu, b, o);
        }
        if (l == 0) { ST[0] = a; ST[1] = b; }
    }
    cluster.sync();    // also publishes mbar init to peers
    if (tid == 0) {
        float S = 0.f, Q = 0.f;
#pragma unroll
        for (int c = 0; c < 4; c++) {
            const float* r = (const float*)cluster.map_shared_rank((void*)ST, c);
            S += r[0]; Q += r[1];
        }
        const float inv = 1.0f / (float)(NN_ * TT);
        float m = S * inv;
        float var = Q * inv - m * m;
        float istd = rsqrtf(var + 1e-5f);
        ST[2] = m;
        ST[3] = gamma_p[0] * istd;
        ST[4] = beta_p[0];
    }
    __syncthreads();
    const float mean = ST[2], gi = ST[3], bta = ST[4];

    // ---- E = exp(norm(s)), zero padding cols ----
#pragma unroll
    for (int r = 0; r < 5; r++) {
#pragma unroll
        for (int j = 0; j < 5; j++) {
            const int t0 = 2 * l + 64 * j;
            float2 v = upk(E2[r][j]);
            float ex = (t0     < TT) ? expf(fmaf(v.x - mean, gi, bta)) : 0.f;
            float ey = (t0 + 1 < TT) ? expf(fmaf(v.y - mean, gi, bta)) : 0.f;
            E2[r][j] = pack2(ex, ey);
        }
    }
    if (tid < 320) Cv[tid] = (tid < TT) ? 1.0f : 0.f;
    __syncthreads();

    float ru[5];
#pragma unroll
    for (int r = 0; r < 5; r++) ru[r] = 0.f;

    // ---- sinkhorn iterations (early exit, cap 100) ----
    for (int k = 0; k < 100; k++) {
        const int buf = k & 1;
        const uint32_t par = (uint32_t)((k >> 1) & 1);

        // row pass: ru[r] = 1 / sum_t E[r,t]*Cv[t]
        ull cv2[5];
#pragma unroll
        for (int j = 0; j < 5; j++) cv2[j] = *(const ull*)&Cv[2 * l + 64 * j];
#pragma unroll
        for (int r = 0; r < 5; r++) {
            ull a2 = 0ull;
#pragma unroll
            for (int j = 0; j < 5; j++) fma2(a2, E2[r][j], cv2[j]);
            float2 p = upk(a2);
            float a = p.x + p.y;
#pragma unroll
            for (int o = 16; o; o >>= 1) a += __shfl_xor_sync(0xffffffffu, a, o);
            ru[r] = 1.0f / a;
        }
        // col partials over own rows
        ull cp2[5] = {0ull, 0ull, 0ull, 0ull, 0ull};
#pragma unroll
        for (int r = 0; r < 5; r++) {
            ull rr = dup2(ru[r]);
#pragma unroll
            for (int j = 0; j < 5; j++) fma2(cp2[j], E2[r][j], rr);
        }
#pragma unroll
        for (int j = 0; j < 5; j++) *(ull*)&CP[w][2 * l + 64 * j] = cp2[j];
        if (tid == 0) NC2[buf] = 0;    // readers of NC2[buf] were at iter k-2: safe
        __syncthreads();

        // CTA-local reduce over 20 warps, store own slot, push to 3 peers
        if (tid < 320) {
            float tot = 0.f;
#pragma unroll
            for (int ww = 0; ww < 20; ww++) tot += CP[ww][tid];
            RCV[buf][crank][tid] = tot;
            const uint32_t off = (uint32_t)(((buf * 4 + crank) * 320 + tid) * 4);
#pragma unroll
            for (int i = 0; i < 3; i++) st_cluster_f32(r_rcv[i] + off, tot);
        }
        __syncthreads();
        if (tid < 3) {                 // one arrive per peer, release-ordered
            fence_cluster();
            mbar_arrive_cluster(r_mb[tid] + (uint32_t)(buf * 8));
        }
        mbar_wait_parity(mb_u32 + (uint32_t)(buf * 8), par);

        if (tid < 320) {
            fence_cluster();           // acquire side for peer stores
            // rank-order sum -> bit-identical Cv in all 4 CTAs
            float tt = RCV[buf][0][tid] + RCV[buf][1][tid]
                     + RCV[buf][2][tid] + RCV[buf][3][tid];
            float nv = (tid < TT) ? 1.0f / tt : 0.f;
            if (tid < TT) {
                float ov = Cv[tid];
                if (fabsf(nv - ov) > 1e-5f * fabsf(ov)) NC2[buf] = 1;
            }
            Cv[tid] = nv;
        }
        __syncthreads();
        if (NC2[buf] == 0) break;      // identical decision in all 4 cluster CTAs
    }

    // ---- write s1 = E * ru * cv ----
    ull cv2[5];
#pragma unroll
    for (int j = 0; j < 5; j++) cv2[j] = *(const ull*)&Cv[2 * l + 64 * j];
#pragma unroll
    for (int r = 0; r < 5; r++) {
        const float rr = ru[r];
        float* rp = gbase + r * TP;
#pragma unroll
        for (int j = 0; j < 5; j++) {
            float2 e = upk(E2[r][j]);
            float2 c = upk(cv2[j]);
            *(float2*)(rp + 2 * l + 64 * j) = make_float2(e.x * rr * c.x, e.y * rr * c.y);
        }
    }
    cluster.sync();   // keep SMEM alive until all peer traffic fully drains
}

// ============================================================================
// head: pred[i] = h[i,:] @ Wo + bo   (one warp per output row)
// ============================================================================
__global__ void head_kernel(const float* __restrict__ h, const float* __restrict__ Wo,
                            const float* __restrict__ bo, float* __restrict__ out, int total) {
    int gwarp = (blockIdx.x * blockDim.x + threadIdx.x) >> 5;
    int lane = threadIdx.x & 31;
    if (gwarp >= total) return;
    const float* hp = h + (size_t)gwarp * HH;
    float acc = 0.f;
#pragma unroll
    for (int i = lane; i < HH; i += 32) acc += hp[i] * Wo[i];
#pragma unroll
    for (int o = 16; o; o >>= 1) acc += __shfl_xor_sync(0xffffffffu, acc, o);
    if (lane == 0) out[gwarp] = acc + bo[0];
}

// ============================================================================
extern "C" void kernel_launch(void* const* d_in, const int* in_sizes, int n_in,
                              void* d_out, int out_size) {
    (void)in_sizes; (void)n_in; (void)out_size;
    const float* features = (const float*)d_in[0];   // [B, N, D]
    const float* text     = (const float*)d_in[1];   // [T, D]
    const float* Amat     = (const float*)d_in[2];   // [D, D]
    const float* gamma    = (const float*)d_in[3];
    const float* beta     = (const float*)d_in[4];
    const float* Wh       = (const float*)d_in[5];   // [2D, H]
    const float* bh       = (const float*)d_in[6];   // [H]
    const float* Wo       = (const float*)d_in[7];   // [H, 1]
    const float* bo       = (const float*)d_in[8];   // [1]
    float* out = (float*)d_out;                      // [B, T]

    float *tA, *sbuf, *f1, *th, *hbuf;
    cudaGetSymbolAddress((void**)&tA,   g_tA);
    cudaGetSymbolAddress((void**)&sbuf, g_s);
    cudaGetSymbolAddress((void**)&f1,   g_f1);
    cudaGetSymbolAddress((void**)&th,   g_th);
    cudaGetSymbolAddress((void**)&hbuf, g_h);

    dim3 b256(256);

    // tA[t,d] = sum_e text[t,e] * A[d,e]      (NT, M=315 N=512 K=512)
    gemm_nt_kernel<<<dim3(5, 8), b256>>>(text, Amat, tA, TT, DD, DD, DD, DD);

    // s[b*n, t] = features @ tA^T             (NT, M=12800 N=315 K=512, ldc=TP,
    //                                          cols 315..319 stored as exact zeros)
    gemm_nt_kernel<<<dim3(200, 5), b256>>>(
        features, tA, sbuf, BB * NN_, TT, DD, TP, TP);

    // instance-norm + sinkhorn (push-based exchange, early-exit @1e-5), in place
    sinkhorn_kernel<<<BB * 4, 640>>>(sbuf, gamma, beta);

    // features1[b,t,d] = sum_n s1[b,n,t] * features[b,n,d]   (TN, batched)
    gemm_tn_kernel<<<dim3(5, 8, BB), b256>>>(
        sbuf, features, f1, TT, DD, NN_, TP, DD, DD,
        (long long)NN_ * TP, (long long)NN_ * DD, (long long)TT * DD);

    // th[t,h] = text @ Wh_bottom              (NN, M=315 N=256 K=512)
    gemm_nn_kernel<0><<<dim3(5, 4), b256>>>(
        text, Wh + (size_t)DD * HH, th, TT, HH, DD, nullptr, nullptr);

    // h = relu(f1 @ Wh_top + th + bh)         (NN + epilogue, M=10080 N=256 K=512)
    gemm_nn_kernel<1><<<dim3(158, 4), b256>>>(
        f1, Wh, hbuf, BB * TT, HH, DD, th, bh);

    // pred = h @ Wo + bo
    head_kernel<<<(BB * TT * 32 + 255) / 256, 256>>>(hbuf, Wo, bo, out, BB * TT);
}